// round 13
// baseline (speedup 1.0000x reference)
#include <cuda_runtime.h>

// ---------------- scratch ----------------
// y1 de-interleaved: [n][ci24][33 rows][36]; stored row = y1row+1;
// off j in [0,16): col 2j ("ev"); off 16+j, j in [0,17): col 2j-1 ("od", j=0 pad, never written -> 0)
__device__ float g_y1[32 * 24 * 33 * 36];
__device__ float g_y2[32 * 24 * 16 * 16];
__device__ float g_p1s[24 * 128];         // key n*4+q
__device__ float g_p1q[24 * 128];
__device__ float g_p2s[24 * 128];         // key n*4+q
__device__ float g_p2q[24 * 128];
__device__ float g_hpart[32 * 4 * 2];
__device__ unsigned g_done[32];           // zero-init, self-reset

__device__ __forceinline__ float warp_sum(float v) {
#pragma unroll
    for (int o = 16; o > 0; o >>= 1) v += __shfl_down_sync(0xffffffffu, v, o);
    return v;
}

__device__ __forceinline__ void compute_bn24(const float* __restrict__ ps,
                                             const float* __restrict__ pq,
                                             int np, float invM,
                                             const float* __restrict__ gamma,
                                             const float* __restrict__ beta,
                                             float* s_a, float* s_c, int t) {
    if (t < 192) {
        int c = t >> 3, g = t & 7;
        float s = 0.f, q = 0.f;
        for (int i = g; i < np; i += 8) { s += ps[c * np + i]; q += pq[c * np + i]; }
#pragma unroll
        for (int o = 4; o > 0; o >>= 1) {
            s += __shfl_down_sync(0xffffffffu, s, o, 8);
            q += __shfl_down_sync(0xffffffffu, q, o, 8);
        }
        if (g == 0) {
            float mean = s * invM;
            float var  = q * invM - mean * mean;
            float a    = gamma[c] * rsqrtf(var + 1e-5f);
            s_a[c] = a;
            s_c[c] = beta[c] - mean * a;
        }
    }
}

// ============================== conv1 kernel ==============================
// 128 blocks = 32n x 4 quarters (8 out rows). 512 thr: px = t&255 (8x32),
// hs = t>>8 -> co 0..11 / 12..23. Input rows 16q-1..16q+15 staged once.
#define EV1 0            // [3][17][32] 1632
#define OD1 1632         // [3][17][33] 1683 (col0 pad)
#define W1  3316         // [(ci*3+kh)*3+kw][24] 648
#define RD1 3964         // [24][8][2] 384

__global__ void __launch_bounds__(512, 1) conv1_kernel(
    const float* __restrict__ image, const float* __restrict__ w1) {
    __shared__ __align__(16) float sm[4348];
    const int bid = blockIdx.x, t = threadIdx.x;
    const int warp = t >> 5, lane = t & 31;
    const int n = bid >> 2, qq = bid & 3;

    // stage input rows 16q-1..16q+15 (17) x 64 cols x 3 ci = 816 quads
#pragma unroll
    for (int i = 0; i < 2; i++) {
        int idx = t + i * 512;
        if (idx < 816) {
            int ci  = idx / 272;
            int rem = idx - ci * 272;
            int row = rem >> 4, c4 = rem & 15;
            int hg  = 16 * qq - 1 + row;
            float4 v = make_float4(0.f, 0.f, 0.f, 0.f);
            if (hg >= 0)
                v = *reinterpret_cast<const float4*>(
                    &image[((n * 3 + ci) * 64 + hg) * 64 + c4 * 4]);
            *reinterpret_cast<float2*>(&sm[EV1 + ci * 544 + row * 32 + 2 * c4]) =
                make_float2(v.x, v.z);
            sm[OD1 + ci * 561 + row * 33 + 2 * c4 + 1] = v.y;
            sm[OD1 + ci * 561 + row * 33 + 2 * c4 + 2] = v.w;
        }
    }
    if (t < 51) sm[OD1 + (t / 17) * 561 + (t % 17) * 33] = 0.f;
    // weights: [(ci*3+kh)*3+kw][co24]
    for (int idx = t; idx < 648; idx += 512) {
        int co = idx / 27, rem = idx % 27;
        int ci = rem / 9, kh = (rem % 9) / 3, kw = rem % 3;
        sm[W1 + ((ci * 3 + kh) * 3 + kw) * 24 + co] = w1[co * 27 + rem];
    }
    __syncthreads();

    const int px = t & 255;
    const int r = px >> 5, wo = px & 31;
    const int hs = t >> 8;
    float acc[12];
#pragma unroll
    for (int co = 0; co < 12; co++) acc[co] = 0.f;

#pragma unroll 1
    for (int ci = 0; ci < 3; ci++) {
#pragma unroll
        for (int kh = 0; kh < 3; kh++) {
            const int rl = 2 * r + kh;
            float vv[3];
            vv[0] = sm[OD1 + ci * 561 + rl * 33 + wo];
            vv[1] = sm[EV1 + ci * 544 + rl * 32 + wo];
            vv[2] = sm[OD1 + ci * 561 + rl * 33 + wo + 1];
#pragma unroll
            for (int kw = 0; kw < 3; kw++) {
                float v = vv[kw];
                const float4* wp = reinterpret_cast<const float4*>(
                    &sm[W1 + ((ci * 3 + kh) * 3 + kw) * 24 + hs * 12]);
                float4 a = wp[0], b = wp[1], c = wp[2];
                acc[0] += v * a.x;  acc[1] += v * a.y;  acc[2]  += v * a.z;  acc[3]  += v * a.w;
                acc[4] += v * b.x;  acc[5] += v * b.y;  acc[6]  += v * b.z;  acc[7]  += v * b.w;
                acc[8] += v * c.x;  acc[9] += v * c.y;  acc[10] += v * c.z;  acc[11] += v * c.w;
            }
        }
    }

    {
        const int off = (wo & 1) ? (17 + (wo >> 1)) : (wo >> 1);
        const int row_s = 8 * qq + r + 1;
#pragma unroll
        for (int co = 0; co < 12; co++)
            g_y1[((n * 24 + hs * 12 + co) * 33 + row_s) * 36 + off] = acc[co];
    }

#pragma unroll
    for (int co = 0; co < 12; co++) {
        float rs = warp_sum(acc[co]);
        float rq = warp_sum(acc[co] * acc[co]);
        if (lane == 0) {
            int cglob = hs * 12 + co, w8 = warp & 7;
            sm[RD1 + cglob * 16 + w8 * 2] = rs;
            sm[RD1 + cglob * 16 + w8 * 2 + 1] = rq;
        }
    }
    __syncthreads();
    if (t < 24) {
        float s = 0.f, q = 0.f;
#pragma unroll
        for (int w = 0; w < 8; w++) { s += sm[RD1 + t * 16 + w * 2]; q += sm[RD1 + t * 16 + w * 2 + 1]; }
        g_p1s[t * 128 + n * 4 + qq] = s;
        g_p1q[t * 128 + n * 4 + qq] = q;
    }
}

// ============================== conv2 kernel ==============================
// 128 blocks = 32n x 4 quarters (4 out rows), ALL 24 co.
// 512 thr: px = t&63 (4 rows x 16 cols), grp = t>>6 (0..7) -> 3 co each.
// Quad input layout per ci: [9 rows][16 quads] of (v0,v1,v2,_).
#define TQ  0            // 6 ci x 576 = 3456
#define W2  3456         // [((ci*3+kh)*8+grp)][12] 6912
#define A2  10368
#define C2  10392
#define RD2 10416        // [24][2][2] 96

struct StageV { float fe[4]; float fo[5]; int dst; };

__device__ __forceinline__ void stage_quad_load(int n, int qq, int ck, int idx,
                                                const float* sA, const float* sC,
                                                StageV& sv) {
    int ci_l = idx / 36;
    int rem  = idx - ci_l * 36;
    int rr   = rem >> 2, jg = (rem & 3) << 2;
    int ci   = ck * 6 + ci_l;
    const float* rowp = &g_y1[((n * 24 + ci) * 33 + 8 * qq + rr) * 36];
    float4 ev  = *reinterpret_cast<const float4*>(rowp + jg);
    float4 od4 = *reinterpret_cast<const float4*>(rowp + 16 + jg);
    float  od5 = rowp[20 + jg];
    float a = sA[ci], c = sC[ci];
    sv.fe[0] = fmaxf(fmaf(a, ev.x, c), 0.f);
    sv.fe[1] = fmaxf(fmaf(a, ev.y, c), 0.f);
    sv.fe[2] = fmaxf(fmaf(a, ev.z, c), 0.f);
    sv.fe[3] = fmaxf(fmaf(a, ev.w, c), 0.f);
    sv.fo[0] = fmaxf(fmaf(a, od4.x, c), 0.f);
    sv.fo[1] = fmaxf(fmaf(a, od4.y, c), 0.f);
    sv.fo[2] = fmaxf(fmaf(a, od4.z, c), 0.f);
    sv.fo[3] = fmaxf(fmaf(a, od4.w, c), 0.f);
    sv.fo[4] = fmaxf(fmaf(a, od5, c), 0.f);
    if (jg == 0) sv.fo[0] = 0.f;                       // col -1 pad
    if (qq + rr == 0) {                                // y1 row -1 pad
#pragma unroll
        for (int i = 0; i < 4; i++) sv.fe[i] = 0.f;
#pragma unroll
        for (int i = 0; i < 5; i++) sv.fo[i] = 0.f;
    }
    sv.dst = ci_l * 576 + rr * 64 + jg * 4;
}

__device__ __forceinline__ void stage_quad_store(float* smem, const StageV& sv) {
#pragma unroll
    for (int k = 0; k < 4; k++)
        *reinterpret_cast<float4*>(&smem[TQ + sv.dst + k * 4]) =
            make_float4(sv.fo[k], sv.fe[k], sv.fo[k + 1], 0.f);
}

__global__ void __launch_bounds__(512, 1) conv2_kernel(
    const float* __restrict__ w2,
    const float* __restrict__ bn1_g, const float* __restrict__ bn1_b) {
    __shared__ __align__(16) float sm[10512];
    const int bid = blockIdx.x, t = threadIdx.x;
    const int warp = t >> 5, lane = t & 31;
    const int n = bid >> 2, qq = bid & 3;

    compute_bn24(g_p1s, g_p1q, 128, 1.f / 32768.f, bn1_g, bn1_b, &sm[A2], &sm[C2], t);

    // weights: [((ci*3+kh)*8+grp)][c3*3+kw], all 24co x 24ci x 9 = 5184
    for (int idx = t; idx < 5184; idx += 512) {
        int co = idx / 216, rem = idx % 216;
        int ci = rem / 9, kh = (rem % 9) / 3, kw = rem % 3;
        sm[W2 + ((ci * 3 + kh) * 8 + co / 3) * 12 + (co % 3) * 3 + kw] =
            w2[(co * 24 + ci) * 9 + kh * 3 + kw];
    }
    __syncthreads();   // BN consts ready

    const int px = t & 63;
    const int r = px >> 4, wo = px & 15;
    const int grp = t >> 6;

    if (t < 216) {
        StageV sv;
        stage_quad_load(n, qq, 0, t, &sm[A2], &sm[C2], sv);
        stage_quad_store(sm, sv);
    }
    __syncthreads();

    float acc0 = 0.f, acc1 = 0.f, acc2 = 0.f;

#pragma unroll 1
    for (int ck = 0; ck < 4; ck++) {
        StageV sv;
        const bool pf = (ck < 3) && (t < 216);
        if (pf) stage_quad_load(n, qq, ck + 1, t, &sm[A2], &sm[C2], sv);

#pragma unroll 2
        for (int cil = 0; cil < 6; cil++) {
            const int ci = ck * 6 + cil;
#pragma unroll
            for (int kh = 0; kh < 3; kh++) {
                const int rl = 2 * r + kh;
                float4 q4 = *reinterpret_cast<const float4*>(
                    &sm[TQ + cil * 576 + rl * 64 + wo * 4]);
                const float* wb = &sm[W2 + ((ci * 3 + kh) * 8 + grp) * 12];
                float4 wa = *reinterpret_cast<const float4*>(wb);
                float4 wc = *reinterpret_cast<const float4*>(wb + 4);
                float w8 = wb[8];
                acc0 += q4.x * wa.x + q4.y * wa.y + q4.z * wa.z;
                acc1 += q4.x * wa.w + q4.y * wc.x + q4.z * wc.y;
                acc2 += q4.x * wc.z + q4.y * wc.w + q4.z * w8;
            }
        }
        __syncthreads();
        if (pf) stage_quad_store(sm, sv);
        __syncthreads();
    }

    const int ho = 4 * qq + r;
    const int cb = grp * 3;
    g_y2[((n * 24 + cb + 0) * 16 + ho) * 16 + wo] = acc0;
    g_y2[((n * 24 + cb + 1) * 16 + ho) * 16 + wo] = acc1;
    g_y2[((n * 24 + cb + 2) * 16 + ho) * 16 + wo] = acc2;

    float av[3] = {acc0, acc1, acc2};
#pragma unroll
    for (int c3 = 0; c3 < 3; c3++) {
        float rs = warp_sum(av[c3]);
        float rq = warp_sum(av[c3] * av[c3]);
        if (lane == 0) {
            int ch = grp * 3 + c3, w2i = warp & 1;
            sm[RD2 + ch * 4 + w2i * 2] = rs;
            sm[RD2 + ch * 4 + w2i * 2 + 1] = rq;
        }
    }
    __syncthreads();
    if (t < 24) {
        float s = sm[RD2 + t * 4] + sm[RD2 + t * 4 + 2];
        float q = sm[RD2 + t * 4 + 1] + sm[RD2 + t * 4 + 3];
        g_p2s[t * 128 + n * 4 + qq] = s;
        g_p2q[t * 128 + n * 4 + qq] = q;
    }
}

// ============================== head kernel ==============================
#define HQ   0
#define HA   128
#define HC   152
#define HP   176         // 24*16
#define HS   560
#define HRA  592
#define HRB  720
#define HR   1232
#define HH   1360
#define HO   1872

__global__ void __launch_bounds__(512, 1) head_kernel(
    const float* __restrict__ ques,
    const float* __restrict__ bn2_g, const float* __restrict__ bn2_b,
    const float* __restrict__ w_rel, const float* __restrict__ b_rel,
    const float* __restrict__ w_fc1, const float* __restrict__ b_fc1,
    const float* __restrict__ w_fc2, const float* __restrict__ b_fc2,
    float* __restrict__ out) {
    __shared__ __align__(16) float sm[1888];
    const int bid = blockIdx.x, t = threadIdx.x;
    const int warp = t >> 5, lane = t & 31;
    const int n = bid >> 2, chunk = bid & 3;

    compute_bn24(g_p2s, g_p2q, 128, 1.f / 8192.f, bn2_g, bn2_b, &sm[HA], &sm[HC], t);
    if (t >= 384) sm[HQ + t - 384] = ques[n * 128 + t - 384];
    __syncthreads();

    if (t < 384) {
        int c = t >> 4, g = t & 15;
        const float* yp = &g_y2[(n * 24 + c) * 256 + g * 16];
        float a = sm[HA + c], cc = sm[HC + c];
        float acc = 0.f;
#pragma unroll
        for (int i = 0; i < 16; i++) acc += fmaxf(fmaf(a, yp[i], cc), 0.f);
        sm[HP + c * 16 + g] = acc;
    }
    __syncthreads();
    if (t < 26) {
        float s = 0.f;
        if (t < 24) {
#pragma unroll
            for (int g = 0; g < 16; g++) s += sm[HP + t * 16 + g];
        }
        sm[HS + t] = s;
    }
    __syncthreads();

    {
        const int j = t & 127, kk = t >> 7;
        float r2 = (kk == 0) ? b_rel[j] : 0.f;
        const float* wq = &w_rel[(52 + kk * 32) * 128 + j];
#pragma unroll 8
        for (int q = 0; q < 32; q++)
            r2 = fmaf(sm[HQ + kk * 32 + q], wq[q * 128], r2);
        sm[HRB + kk * 128 + j] = r2;
        if (kk == 0) {
            float r1 = 0.f;
#pragma unroll
            for (int k = 0; k < 26; k++)
                r1 += sm[HS + k] * (w_rel[k * 128 + j] + w_rel[(26 + k) * 128 + j]);
            sm[HRA + j] = r1;
        }
    }
    __syncthreads();
    if (t < 128)
        sm[HR + t] = 256.f * sm[HRA + t] +
                     65536.f * (sm[HRB + t] + sm[HRB + 128 + t] +
                                sm[HRB + 256 + t] + sm[HRB + 384 + t]);
    __syncthreads();

    {
        const int jj = t & 255, kh2 = t >> 8;
        const int j = chunk * 256 + jj;
        float acc = (kh2 == 0) ? b_fc1[j] : 0.f;
        const float* wp = &w_fc1[(kh2 * 64) * 1024 + j];
        const float* rp = &sm[HR + kh2 * 64];
#pragma unroll 16
        for (int k = 0; k < 64; k++)
            acc = fmaf(rp[k], wp[k * 1024], acc);
        sm[HH + t] = acc;
    }
    __syncthreads();
    {
        float p0 = 0.f, p1 = 0.f;
        if (t < 256) {
            float hv = fmaxf(sm[HH + t] + sm[HH + t + 256], 0.f);
            const int j = chunk * 256 + t;
            p0 = hv * w_fc2[j * 2];
            p1 = hv * w_fc2[j * 2 + 1];
        }
        p0 = warp_sum(p0);
        p1 = warp_sum(p1);
        if (lane == 0 && warp < 8) { sm[HO + warp * 2] = p0; sm[HO + warp * 2 + 1] = p1; }
    }
    __syncthreads();
    if (t == 0) {
        float o0 = 0.f, o1 = 0.f;
#pragma unroll
        for (int w = 0; w < 8; w++) { o0 += sm[HO + w * 2]; o1 += sm[HO + w * 2 + 1]; }
        g_hpart[(n * 4 + chunk) * 2 + 0] = o0;
        g_hpart[(n * 4 + chunk) * 2 + 1] = o1;
        __threadfence();
        unsigned r = atomicAdd(&g_done[n], 1u);
        if (r == 3) {
            __threadfence();
            float f0 = b_fc2[0], f1 = b_fc2[1];
#pragma unroll
            for (int c = 0; c < 4; c++) {
                f0 += g_hpart[(n * 4 + c) * 2 + 0];
                f1 += g_hpart[(n * 4 + c) * 2 + 1];
            }
            out[n * 2 + 0] = f0;
            out[n * 2 + 1] = f1;
            g_done[n] = 0;
        }
    }
}

// ---------------- launch ----------------
extern "C" void kernel_launch(void* const* d_in, const int* in_sizes, int n_in,
                              void* d_out, int out_size) {
    (void)in_sizes; (void)n_in; (void)out_size;
    const float* image   = (const float*)d_in[0];
    const float* ques    = (const float*)d_in[1];
    const float* conv1_w = (const float*)d_in[2];
    const float* bn1_g   = (const float*)d_in[4];
    const float* bn1_b   = (const float*)d_in[5];
    const float* conv2_w = (const float*)d_in[6];
    const float* bn2_g   = (const float*)d_in[8];
    const float* bn2_b   = (const float*)d_in[9];
    const float* w_rel   = (const float*)d_in[10];
    const float* b_rel   = (const float*)d_in[11];
    const float* w_fc1   = (const float*)d_in[12];
    const float* b_fc1   = (const float*)d_in[13];
    const float* w_fc2   = (const float*)d_in[14];
    const float* b_fc2   = (const float*)d_in[15];
    float* out = (float*)d_out;

    conv1_kernel<<<128, 512>>>(image, conv1_w);
    conv2_kernel<<<128, 512>>>(conv2_w, bn1_g, bn1_b);
    head_kernel<<<128, 512>>>(ques, bn2_g, bn2_b, w_rel, b_rel,
                              w_fc1, b_fc1, w_fc2, b_fc2, out);
}

// round 14
// speedup vs baseline: 1.0672x; 1.0672x over previous
#include <cuda_runtime.h>

// ---------------- scratch ----------------
// y1 de-interleaved: [n][ci24][33 rows][36]; stored row = y1row+1;
// off j in [0,16): col 2j ("ev"); off 16+j, j in [0,17): col 2j-1 ("od", j=0 pad)
__device__ float g_y1[32 * 24 * 33 * 36];
__device__ float g_y2[32 * 24 * 16 * 16];
__device__ float g_p1s[24 * 64];          // key n*2+h16
__device__ float g_p1q[24 * 64];
__device__ float g_p2s[24 * 64];          // key n*2+half
__device__ float g_p2q[24 * 64];
__device__ float g_hpart[32 * 4 * 2];
__device__ unsigned g_done[32];           // zero-init, self-reset

__device__ __forceinline__ float warp_sum(float v) {
#pragma unroll
    for (int o = 16; o > 0; o >>= 1) v += __shfl_down_sync(0xffffffffu, v, o);
    return v;
}

__device__ __forceinline__ void compute_bn24(const float* __restrict__ ps,
                                             const float* __restrict__ pq,
                                             float invM,
                                             const float* __restrict__ gamma,
                                             const float* __restrict__ beta,
                                             float* s_a, float* s_c, int t) {
    if (t < 192) {
        int c = t >> 3, g = t & 7;
        float s = 0.f, q = 0.f;
        for (int i = g; i < 64; i += 8) { s += ps[c * 64 + i]; q += pq[c * 64 + i]; }
#pragma unroll
        for (int o = 4; o > 0; o >>= 1) {
            s += __shfl_down_sync(0xffffffffu, s, o, 8);
            q += __shfl_down_sync(0xffffffffu, q, o, 8);
        }
        if (g == 0) {
            float mean = s * invM;
            float var  = q * invM - mean * mean;
            float a    = gamma[c] * rsqrtf(var + 1e-5f);
            s_a[c] = a;
            s_c[c] = beta[c] - mean * a;
        }
    }
}

// ============================== conv1 kernel ==============================
// 128 blocks = 32n x 2 h16 x 2 cg(12co). 512 thr = 16 out rows x 32 cols.
#define EV1 0            // [3][33][32]  3168
#define OD1 3168         // [3][33][33]  3267 (col0 pad)
#define W1  6448         // [(ci*3+kh)*3+kw][12] 324
#define RD1 6784         // [12][16][2]  384

__global__ void __launch_bounds__(512, 1) conv1_kernel(
    const float* __restrict__ image, const float* __restrict__ w1) {
    __shared__ __align__(16) float sm[7168];
    const int bid = blockIdx.x, t = threadIdx.x;
    const int warp = t >> 5, lane = t & 31;
    const int n = bid >> 2, h16 = (bid >> 1) & 1, cg = bid & 1;

#pragma unroll
    for (int i = 0; i < 4; i++) {
        int idx = t + i * 512;
        if (idx < 1584) {
            int ci  = idx / 528;
            int rem = idx - ci * 528;
            int row = rem >> 4, c4 = rem & 15;
            int hg  = 32 * h16 - 1 + row;
            float4 v = make_float4(0.f, 0.f, 0.f, 0.f);
            if (hg >= 0)
                v = *reinterpret_cast<const float4*>(
                    &image[((n * 3 + ci) * 64 + hg) * 64 + c4 * 4]);
            *reinterpret_cast<float2*>(&sm[EV1 + ci * 1056 + row * 32 + 2 * c4]) =
                make_float2(v.x, v.z);
            sm[OD1 + ci * 1089 + row * 33 + 2 * c4 + 1] = v.y;
            sm[OD1 + ci * 1089 + row * 33 + 2 * c4 + 2] = v.w;
        }
    }
    if (t < 99) sm[OD1 + (t / 33) * 1089 + (t % 33) * 33] = 0.f;
    if (t < 324) {
        int co = t / 27, rem = t % 27;
        int ci = rem / 9, kh = (rem % 9) / 3, kw = rem % 3;
        sm[W1 + ((ci * 3 + kh) * 3 + kw) * 12 + co] = w1[(cg * 12 + co) * 27 + rem];
    }
    __syncthreads();

    const int r = t >> 5, wo = t & 31;
    float acc[12];
#pragma unroll
    for (int co = 0; co < 12; co++) acc[co] = 0.f;

#pragma unroll 1
    for (int ci = 0; ci < 3; ci++) {
        // hoist all 9 inputs for this ci (MLP 9, decouple from FMA chains)
        float iv[3][3];
#pragma unroll
        for (int kh = 0; kh < 3; kh++) {
            const int rl = 2 * r + kh;
            iv[kh][0] = sm[OD1 + ci * 1089 + rl * 33 + wo];
            iv[kh][1] = sm[EV1 + ci * 1056 + rl * 32 + wo];
            iv[kh][2] = sm[OD1 + ci * 1089 + rl * 33 + wo + 1];
        }
#pragma unroll
        for (int kh = 0; kh < 3; kh++) {
            const float4* wp = reinterpret_cast<const float4*>(&sm[W1 + (ci * 3 + kh) * 36]);
#pragma unroll
            for (int kw = 0; kw < 3; kw++) {
                float v = iv[kh][kw];
                float4 a = wp[kw * 3], b = wp[kw * 3 + 1], c = wp[kw * 3 + 2];
                acc[0] += v * a.x;  acc[1] += v * a.y;  acc[2]  += v * a.z;  acc[3]  += v * a.w;
                acc[4] += v * b.x;  acc[5] += v * b.y;  acc[6]  += v * b.z;  acc[7]  += v * b.w;
                acc[8] += v * c.x;  acc[9] += v * c.y;  acc[10] += v * c.z;  acc[11] += v * c.w;
            }
        }
    }

    {
        const int off = (wo & 1) ? (17 + (wo >> 1)) : (wo >> 1);
        const int row_s = 16 * h16 + r + 1;
#pragma unroll
        for (int co = 0; co < 12; co++)
            g_y1[((n * 24 + cg * 12 + co) * 33 + row_s) * 36 + off] = acc[co];
    }

#pragma unroll
    for (int co = 0; co < 12; co++) {
        float rs = warp_sum(acc[co]);
        float rq = warp_sum(acc[co] * acc[co]);
        if (lane == 0) { sm[RD1 + co * 32 + warp * 2] = rs; sm[RD1 + co * 32 + warp * 2 + 1] = rq; }
    }
    __syncthreads();
    if (t < 12) {
        float s = 0.f, q = 0.f;
#pragma unroll
        for (int w = 0; w < 16; w++) { s += sm[RD1 + t * 32 + w * 2]; q += sm[RD1 + t * 32 + w * 2 + 1]; }
        g_p1s[(cg * 12 + t) * 64 + n * 2 + h16] = s;
        g_p1q[(cg * 12 + t) * 64 + n * 2 + h16] = q;
    }
}

// ============================== conv2 kernel ==============================
// 128 blocks = 32n x 2 half x 2 cg. Quad input layout: per ci a [17][16] array
// of float4 quads (v0,v1,v2,_), v's = cols (2j-1, 2j, 2j+1).
#define TQ  0            // 6 ci x 1088 = 6528
#define W2  6528         // [((ci*3+kh)*4+grp)][12] 3456
#define A2  9984
#define C2  10008
#define RD2 10032        // [12][4][2] 96

struct StageV { float fe[4]; float fo[5]; int dst; };

__device__ __forceinline__ void stage_quad_load(int n, int half, int ck, int idx,
                                                const float* sA, const float* sC,
                                                StageV& sv) {
    int ci_l = idx / 68;
    int rem = idx - ci_l * 68;
    int row = rem >> 2, jg = (rem & 3) << 2;
    int ci  = ck * 6 + ci_l;
    const float* rowp = &g_y1[((n * 24 + ci) * 33 + 16 * half + row) * 36];
    float4 ev  = *reinterpret_cast<const float4*>(rowp + jg);
    float4 od4 = *reinterpret_cast<const float4*>(rowp + 16 + jg);
    float  od5 = rowp[20 + jg];
    float a = sA[ci], c = sC[ci];
    sv.fe[0] = fmaxf(fmaf(a, ev.x, c), 0.f);
    sv.fe[1] = fmaxf(fmaf(a, ev.y, c), 0.f);
    sv.fe[2] = fmaxf(fmaf(a, ev.z, c), 0.f);
    sv.fe[3] = fmaxf(fmaf(a, ev.w, c), 0.f);
    sv.fo[0] = fmaxf(fmaf(a, od4.x, c), 0.f);
    sv.fo[1] = fmaxf(fmaf(a, od4.y, c), 0.f);
    sv.fo[2] = fmaxf(fmaf(a, od4.z, c), 0.f);
    sv.fo[3] = fmaxf(fmaf(a, od4.w, c), 0.f);
    sv.fo[4] = fmaxf(fmaf(a, od5, c), 0.f);
    if (jg == 0) sv.fo[0] = 0.f;                       // col -1 pad
    if (half + row == 0) {                             // y1 row -1 pad
#pragma unroll
        for (int i = 0; i < 4; i++) sv.fe[i] = 0.f;
#pragma unroll
        for (int i = 0; i < 5; i++) sv.fo[i] = 0.f;
    }
    sv.dst = ci_l * 1088 + row * 64 + jg * 4;
}

__device__ __forceinline__ void stage_quad_store(float* smem, const StageV& sv) {
#pragma unroll
    for (int k = 0; k < 4; k++)
        *reinterpret_cast<float4*>(&smem[TQ + sv.dst + k * 4]) =
            make_float4(sv.fo[k], sv.fe[k], sv.fo[k + 1], 0.f);
}

__global__ void __launch_bounds__(512, 1) conv2_kernel(
    const float* __restrict__ w2,
    const float* __restrict__ bn1_g, const float* __restrict__ bn1_b) {
    __shared__ __align__(16) float sm[10128];
    const int bid = blockIdx.x, t = threadIdx.x;
    const int warp = t >> 5, lane = t & 31;
    const int n = bid >> 2, half = (bid >> 1) & 1, cg = bid & 1;

    compute_bn24(g_p1s, g_p1q, 1.f / 32768.f, bn1_g, bn1_b, &sm[A2], &sm[C2], t);

    for (int idx = t; idx < 2592; idx += 512) {
        int co = idx / 216, rem = idx % 216;
        int ci = rem / 9, kh = (rem % 9) / 3, kw = rem % 3;
        sm[W2 + ((ci * 3 + kh) * 4 + co / 3) * 12 + (co % 3) * 3 + kw] =
            w2[((cg * 12 + co) * 24 + ci) * 9 + kh * 3 + kw];
    }
    __syncthreads();   // BN consts ready

    // conflict-free px mapping: 4 rows x 8 cols per warp
    const int w4 = warp & 3;
    const int grp = t >> 7;
    const int wo = (lane & 7) | ((w4 & 1) << 3);
    const int r  = (lane >> 3) | ((w4 >> 1) << 2);

    // stage chunk 0
    if (t < 408) {
        StageV sv;
        stage_quad_load(n, half, 0, t, &sm[A2], &sm[C2], sv);
        stage_quad_store(sm, sv);
    }
    __syncthreads();

    float acc0 = 0.f, acc1 = 0.f, acc2 = 0.f;

#pragma unroll 1
    for (int ck = 0; ck < 4; ck++) {
        StageV sv;
        const bool pf = (ck < 3) && (t < 408);
        if (pf) stage_quad_load(n, half, ck + 1, t, &sm[A2], &sm[C2], sv);

#pragma unroll 2
        for (int cil = 0; cil < 6; cil++) {
            const int ci = ck * 6 + cil;
            // hoist the 3 kh-quads (MLP 3, decouple LDS from FMA)
            float4 q4[3];
#pragma unroll
            for (int kh = 0; kh < 3; kh++)
                q4[kh] = *reinterpret_cast<const float4*>(
                    &sm[TQ + cil * 1088 + (2 * r + kh) * 64 + wo * 4]);
#pragma unroll
            for (int kh = 0; kh < 3; kh++) {
                const float* wb = &sm[W2 + ((ci * 3 + kh) * 4 + grp) * 12];
                float4 wa = *reinterpret_cast<const float4*>(wb);
                float4 wc = *reinterpret_cast<const float4*>(wb + 4);
                float w8 = wb[8];
                acc0 += q4[kh].x * wa.x + q4[kh].y * wa.y + q4[kh].z * wa.z;
                acc1 += q4[kh].x * wa.w + q4[kh].y * wc.x + q4[kh].z * wc.y;
                acc2 += q4[kh].x * wc.z + q4[kh].y * wc.w + q4[kh].z * w8;
            }
        }
        __syncthreads();
        if (pf) stage_quad_store(sm, sv);
        __syncthreads();
    }

    const int ho = half * 8 + r;
    const int cb = cg * 12 + grp * 3;
    g_y2[((n * 24 + cb + 0) * 16 + ho) * 16 + wo] = acc0;
    g_y2[((n * 24 + cb + 1) * 16 + ho) * 16 + wo] = acc1;
    g_y2[((n * 24 + cb + 2) * 16 + ho) * 16 + wo] = acc2;

    float av[3] = {acc0, acc1, acc2};
#pragma unroll
    for (int c3 = 0; c3 < 3; c3++) {
        float rs = warp_sum(av[c3]);
        float rq = warp_sum(av[c3] * av[c3]);
        if (lane == 0) {
            int ch = grp * 3 + c3;
            sm[RD2 + ch * 8 + w4 * 2] = rs;
            sm[RD2 + ch * 8 + w4 * 2 + 1] = rq;
        }
    }
    __syncthreads();
    if (t < 12) {
        float s = 0.f, q = 0.f;
#pragma unroll
        for (int w = 0; w < 4; w++) { s += sm[RD2 + t * 8 + w * 2]; q += sm[RD2 + t * 8 + w * 2 + 1]; }
        g_p2s[(cg * 12 + t) * 64 + n * 2 + half] = s;
        g_p2q[(cg * 12 + t) * 64 + n * 2 + half] = q;
    }
}

// ============================== head kernel ==============================
#define HQ   0
#define HA   128
#define HC   152
#define HP   176         // 24*16
#define HS   560
#define HRA  592
#define HRB  720
#define HR   1232
#define HH   1360
#define HO   1872

__global__ void __launch_bounds__(512, 1) head_kernel(
    const float* __restrict__ ques,
    const float* __restrict__ bn2_g, const float* __restrict__ bn2_b,
    const float* __restrict__ w_rel, const float* __restrict__ b_rel,
    const float* __restrict__ w_fc1, const float* __restrict__ b_fc1,
    const float* __restrict__ w_fc2, const float* __restrict__ b_fc2,
    float* __restrict__ out) {
    __shared__ __align__(16) float sm[1888];
    const int bid = blockIdx.x, t = threadIdx.x;
    const int warp = t >> 5, lane = t & 31;
    const int n = bid >> 2, chunk = bid & 3;

    compute_bn24(g_p2s, g_p2q, 1.f / 8192.f, bn2_g, bn2_b, &sm[HA], &sm[HC], t);
    if (t >= 384) sm[HQ + t - 384] = ques[n * 128 + t - 384];
    __syncthreads();

    if (t < 384) {
        int c = t >> 4, g = t & 15;
        const float* yp = &g_y2[(n * 24 + c) * 256 + g * 16];
        float a = sm[HA + c], cc = sm[HC + c];
        float acc = 0.f;
#pragma unroll
        for (int i = 0; i < 16; i++) acc += fmaxf(fmaf(a, yp[i], cc), 0.f);
        sm[HP + c * 16 + g] = acc;
    }
    __syncthreads();
    if (t < 26) {
        float s = 0.f;
        if (t < 24) {
#pragma unroll
            for (int g = 0; g < 16; g++) s += sm[HP + t * 16 + g];
        }
        sm[HS + t] = s;
    }
    __syncthreads();

    {
        const int j = t & 127, kk = t >> 7;
        float r2 = (kk == 0) ? b_rel[j] : 0.f;
        const float* wq = &w_rel[(52 + kk * 32) * 128 + j];
#pragma unroll 8
        for (int q = 0; q < 32; q++)
            r2 = fmaf(sm[HQ + kk * 32 + q], wq[q * 128], r2);
        sm[HRB + kk * 128 + j] = r2;
        if (kk == 0) {
            float r1 = 0.f;
#pragma unroll
            for (int k = 0; k < 26; k++)
                r1 += sm[HS + k] * (w_rel[k * 128 + j] + w_rel[(26 + k) * 128 + j]);
            sm[HRA + j] = r1;
        }
    }
    __syncthreads();
    if (t < 128)
        sm[HR + t] = 256.f * sm[HRA + t] +
                     65536.f * (sm[HRB + t] + sm[HRB + 128 + t] +
                                sm[HRB + 256 + t] + sm[HRB + 384 + t]);
    __syncthreads();

    {
        const int jj = t & 255, kh2 = t >> 8;
        const int j = chunk * 256 + jj;
        float acc = (kh2 == 0) ? b_fc1[j] : 0.f;
        const float* wp = &w_fc1[(kh2 * 64) * 1024 + j];
        const float* rp = &sm[HR + kh2 * 64];
#pragma unroll 16
        for (int k = 0; k < 64; k++)
            acc = fmaf(rp[k], wp[k * 1024], acc);
        sm[HH + t] = acc;
    }
    __syncthreads();
    {
        float p0 = 0.f, p1 = 0.f;
        if (t < 256) {
            float hv = fmaxf(sm[HH + t] + sm[HH + t + 256], 0.f);
            const int j = chunk * 256 + t;
            p0 = hv * w_fc2[j * 2];
            p1 = hv * w_fc2[j * 2 + 1];
        }
        p0 = warp_sum(p0);
        p1 = warp_sum(p1);
        if (lane == 0 && warp < 8) { sm[HO + warp * 2] = p0; sm[HO + warp * 2 + 1] = p1; }
    }
    __syncthreads();
    if (t == 0) {
        float o0 = 0.f, o1 = 0.f;
#pragma unroll
        for (int w = 0; w < 8; w++) { o0 += sm[HO + w * 2]; o1 += sm[HO + w * 2 + 1]; }
        g_hpart[(n * 4 + chunk) * 2 + 0] = o0;
        g_hpart[(n * 4 + chunk) * 2 + 1] = o1;
        __threadfence();
        unsigned r = atomicAdd(&g_done[n], 1u);
        if (r == 3) {
            __threadfence();
            float f0 = b_fc2[0], f1 = b_fc2[1];
#pragma unroll
            for (int c = 0; c < 4; c++) {
                f0 += g_hpart[(n * 4 + c) * 2 + 0];
                f1 += g_hpart[(n * 4 + c) * 2 + 1];
            }
            out[n * 2 + 0] = f0;
            out[n * 2 + 1] = f1;
            g_done[n] = 0;
        }
    }
}

// ---------------- launch ----------------
extern "C" void kernel_launch(void* const* d_in, const int* in_sizes, int n_in,
                              void* d_out, int out_size) {
    (void)in_sizes; (void)n_in; (void)out_size;
    const float* image   = (const float*)d_in[0];
    const float* ques    = (const float*)d_in[1];
    const float* conv1_w = (const float*)d_in[2];
    const float* bn1_g   = (const float*)d_in[4];
    const float* bn1_b   = (const float*)d_in[5];
    const float* conv2_w = (const float*)d_in[6];
    const float* bn2_g   = (const float*)d_in[8];
    const float* bn2_b   = (const float*)d_in[9];
    const float* w_rel   = (const float*)d_in[10];
    const float* b_rel   = (const float*)d_in[11];
    const float* w_fc1   = (const float*)d_in[12];
    const float* b_fc1   = (const float*)d_in[13];
    const float* w_fc2   = (const float*)d_in[14];
    const float* b_fc2   = (const float*)d_in[15];
    float* out = (float*)d_out;

    conv1_kernel<<<128, 512>>>(image, conv1_w);
    conv2_kernel<<<128, 512>>>(conv2_w, bn1_g, bn1_b);
    head_kernel<<<128, 512>>>(ques, bn2_g, bn2_b, w_rel, b_rel,
                              w_fc1, b_fc1, w_fc2, b_fc2, out);
}

// round 15
// speedup vs baseline: 1.1301x; 1.0589x over previous
#include <cuda_runtime.h>

// ---------------- scratch ----------------
// y1 de-interleaved: [n][ci24][33 rows][36]; stored row = y1row+1;
// off j in [0,16): col 2j ("ev"); off 16+j, j in [0,17): col 2j-1 ("od", j=0 pad)
__device__ float g_y1[32 * 24 * 33 * 36];
__device__ float g_y2[32 * 24 * 16 * 16];
__device__ float g_p1s[24 * 64];          // key n*2+h16
__device__ float g_p1q[24 * 64];
__device__ float g_p2s[24 * 64];          // key n*2+half
__device__ float g_p2q[24 * 64];
__device__ float g_hpart[32 * 4 * 2];
__device__ unsigned g_done[32];           // zero-init, self-reset

__device__ __forceinline__ float warp_sum(float v) {
#pragma unroll
    for (int o = 16; o > 0; o >>= 1) v += __shfl_down_sync(0xffffffffu, v, o);
    return v;
}

__device__ __forceinline__ void compute_bn24(const float* __restrict__ ps,
                                             const float* __restrict__ pq,
                                             float invM,
                                             const float* __restrict__ gamma,
                                             const float* __restrict__ beta,
                                             float* s_a, float* s_c, int t) {
    if (t < 192) {
        int c = t >> 3, g = t & 7;
        float s = 0.f, q = 0.f;
        for (int i = g; i < 64; i += 8) { s += ps[c * 64 + i]; q += pq[c * 64 + i]; }
#pragma unroll
        for (int o = 4; o > 0; o >>= 1) {
            s += __shfl_down_sync(0xffffffffu, s, o, 8);
            q += __shfl_down_sync(0xffffffffu, q, o, 8);
        }
        if (g == 0) {
            float mean = s * invM;
            float var  = q * invM - mean * mean;
            float a    = gamma[c] * rsqrtf(var + 1e-5f);
            s_a[c] = a;
            s_c[c] = beta[c] - mean * a;
        }
    }
}

// packed f32x2 helpers
#define FMA2(acc, v, w) \
    asm("fma.rn.f32x2 %0, %1, %2, %0;" : "+l"(acc) : "l"(v), "l"(w))

__device__ __forceinline__ unsigned long long pack2(float lo, float hi) {
    unsigned long long r;
    asm("mov.b64 %0, {%1, %2};" : "=l"(r) : "f"(lo), "f"(hi));
    return r;
}

// ============================== conv1 kernel ==============================
// 128 blocks = 32n x 2 h16 x 2 cg(12co). 512 thr: pair = t&255 (16 rows x 16
// col-pairs), sub = t>>8 -> co 0..5 / 6..11. Each thread: 2 output px packed
// in f32x2, 6 co.
#define EV1 0            // [3][33][32]  3168 (stride 32)
#define OD1 3168         // [3][33][34]  3366 (stride 34, col0 pad)
#define W1  6536         // [(ci*3+kh)*3+kw][2 sub][12] dup'd weights, 648
#define RD1 7184         // [12][8][2] 192

__global__ void __launch_bounds__(512, 1) conv1_kernel(
    const float* __restrict__ image, const float* __restrict__ w1) {
    __shared__ __align__(16) float sm[7376];
    const int bid = blockIdx.x, t = threadIdx.x;
    const int warp = t >> 5, lane = t & 31;
    const int n = bid >> 2, h16 = (bid >> 1) & 1, cg = bid & 1;

    // stage input rows 32*h16-1 .. +31 via float4 (3*33*16 = 1584 quads)
#pragma unroll
    for (int i = 0; i < 4; i++) {
        int idx = t + i * 512;
        if (idx < 1584) {
            int ci  = idx / 528;
            int rem = idx - ci * 528;
            int row = rem >> 4, c4 = rem & 15;
            int hg  = 32 * h16 - 1 + row;
            float4 v = make_float4(0.f, 0.f, 0.f, 0.f);
            if (hg >= 0)
                v = *reinterpret_cast<const float4*>(
                    &image[((n * 3 + ci) * 64 + hg) * 64 + c4 * 4]);
            *reinterpret_cast<float2*>(&sm[EV1 + ci * 1056 + row * 32 + 2 * c4]) =
                make_float2(v.x, v.z);
            sm[OD1 + ci * 1122 + row * 34 + 2 * c4 + 1] = v.y;
            sm[OD1 + ci * 1122 + row * 34 + 2 * c4 + 2] = v.w;
        }
    }
    if (t < 99) sm[OD1 + (t / 33) * 1122 + (t % 33) * 34] = 0.f;
    // weights duplicated (w,w): dst [(ci*3+kh)*3+kw][sub][c*2 .. c*2+1]
    if (t < 324) {
        int co = t / 27, rem = t % 27;
        int ci = rem / 9, kh = (rem % 9) / 3, kw = rem % 3;
        float w = w1[(cg * 12 + co) * 27 + rem];
        int dst = W1 + ((ci * 3 + kh) * 3 + kw) * 24 + (co / 6) * 12 + (co % 6) * 2;
        sm[dst] = w;
        sm[dst + 1] = w;
    }
    __syncthreads();

    const int pair = t & 255;
    const int r = pair >> 4, wp = pair & 15;   // out rows 0..15, col-pairs 0..15
    const int sub = t >> 8;

    unsigned long long acc[6];
#pragma unroll
    for (int c = 0; c < 6; c++) acc[c] = 0ull;

#pragma unroll 1
    for (int ci = 0; ci < 3; ci++) {
        const int bod = OD1 + ci * 1122;
        const int bev = EV1 + ci * 1056;
#pragma unroll
        for (int kh = 0; kh < 3; kh++) {
            const int rl = 2 * r + kh;
            float2 v0f = *reinterpret_cast<const float2*>(&sm[bod + rl * 34 + 2 * wp]);
            float2 v1f = *reinterpret_cast<const float2*>(&sm[bev + rl * 32 + 2 * wp]);
            float  vtf = sm[bod + rl * 34 + 2 * wp + 2];
            unsigned long long v0 = pack2(v0f.x, v0f.y);
            unsigned long long v1 = pack2(v1f.x, v1f.y);
            unsigned long long v2 = pack2(v0f.y, vtf);
#pragma unroll
            for (int kw = 0; kw < 3; kw++) {
                const int wb = W1 + ((ci * 3 + kh) * 3 + kw) * 24 + sub * 12;
                ulonglong2 wA = *reinterpret_cast<const ulonglong2*>(&sm[wb]);
                ulonglong2 wB = *reinterpret_cast<const ulonglong2*>(&sm[wb + 4]);
                ulonglong2 wC = *reinterpret_cast<const ulonglong2*>(&sm[wb + 8]);
                unsigned long long v = (kw == 0) ? v0 : (kw == 1) ? v1 : v2;
                FMA2(acc[0], v, wA.x);
                FMA2(acc[1], v, wA.y);
                FMA2(acc[2], v, wB.x);
                FMA2(acc[3], v, wB.y);
                FMA2(acc[4], v, wC.x);
                FMA2(acc[5], v, wC.y);
            }
        }
    }

    // store y1 de-interleaved + BN partials. px0 = col 2wp (ev off wp),
    // px1 = col 2wp+1 (od off 17+wp).
    {
        const int row_s = 16 * h16 + r + 1;
#pragma unroll
        for (int c = 0; c < 6; c++) {
            float2 a = *reinterpret_cast<float2*>(&acc[c]);
            float* yb = &g_y1[((n * 24 + cg * 12 + sub * 6 + c) * 33 + row_s) * 36];
            yb[wp] = a.x;
            yb[17 + wp] = a.y;
            float rs = warp_sum(a.x + a.y);
            float rq = warp_sum(a.x * a.x + a.y * a.y);
            if (lane == 0) {
                int co12 = sub * 6 + c, w8 = warp & 7;
                sm[RD1 + co12 * 16 + w8 * 2] = rs;
                sm[RD1 + co12 * 16 + w8 * 2 + 1] = rq;
            }
        }
    }
    __syncthreads();
    if (t < 12) {
        float s = 0.f, q = 0.f;
#pragma unroll
        for (int w = 0; w < 8; w++) { s += sm[RD1 + t * 16 + w * 2]; q += sm[RD1 + t * 16 + w * 2 + 1]; }
        g_p1s[(cg * 12 + t) * 64 + n * 2 + h16] = s;
        g_p1q[(cg * 12 + t) * 64 + n * 2 + h16] = q;
    }
}

// ============================== conv2 kernel ==============================
// (round-12 exact) 128 blocks = 32n x 2 half x 2 cg. Quad input layout: per ci
// a [17][16] array of float4 quads (v0,v1,v2,_), v's = cols (2j-1, 2j, 2j+1).
#define TQ  0            // 6 ci x 1088 = 6528
#define W2  6528         // [((ci*3+kh)*4+grp)][12] 3456
#define A2  9984
#define C2  10008
#define RD2 10032        // [12][4][2] 96

struct StageV { float fe[4]; float fo[5]; int dst; };

__device__ __forceinline__ void stage_quad_load(int n, int half, int ck, int idx,
                                                const float* sA, const float* sC,
                                                StageV& sv) {
    int ci_l = idx / 68;
    int rem = idx - ci_l * 68;
    int row = rem >> 2, jg = (rem & 3) << 2;
    int ci  = ck * 6 + ci_l;
    const float* rowp = &g_y1[((n * 24 + ci) * 33 + 16 * half + row) * 36];
    float4 ev  = *reinterpret_cast<const float4*>(rowp + jg);
    float4 od4 = *reinterpret_cast<const float4*>(rowp + 16 + jg);
    float  od5 = rowp[20 + jg];
    float a = sA[ci], c = sC[ci];
    sv.fe[0] = fmaxf(fmaf(a, ev.x, c), 0.f);
    sv.fe[1] = fmaxf(fmaf(a, ev.y, c), 0.f);
    sv.fe[2] = fmaxf(fmaf(a, ev.z, c), 0.f);
    sv.fe[3] = fmaxf(fmaf(a, ev.w, c), 0.f);
    sv.fo[0] = fmaxf(fmaf(a, od4.x, c), 0.f);
    sv.fo[1] = fmaxf(fmaf(a, od4.y, c), 0.f);
    sv.fo[2] = fmaxf(fmaf(a, od4.z, c), 0.f);
    sv.fo[3] = fmaxf(fmaf(a, od4.w, c), 0.f);
    sv.fo[4] = fmaxf(fmaf(a, od5, c), 0.f);
    if (jg == 0) sv.fo[0] = 0.f;                       // col -1 pad
    if (half + row == 0) {                             // y1 row -1 pad
#pragma unroll
        for (int i = 0; i < 4; i++) sv.fe[i] = 0.f;
#pragma unroll
        for (int i = 0; i < 5; i++) sv.fo[i] = 0.f;
    }
    sv.dst = ci_l * 1088 + row * 64 + jg * 4;
}

__device__ __forceinline__ void stage_quad_store(float* smem, const StageV& sv) {
#pragma unroll
    for (int k = 0; k < 4; k++)
        *reinterpret_cast<float4*>(&smem[TQ + sv.dst + k * 4]) =
            make_float4(sv.fo[k], sv.fe[k], sv.fo[k + 1], 0.f);
}

__global__ void __launch_bounds__(512, 1) conv2_kernel(
    const float* __restrict__ w2,
    const float* __restrict__ bn1_g, const float* __restrict__ bn1_b) {
    __shared__ __align__(16) float sm[10128];
    const int bid = blockIdx.x, t = threadIdx.x;
    const int warp = t >> 5, lane = t & 31;
    const int n = bid >> 2, half = (bid >> 1) & 1, cg = bid & 1;

    compute_bn24(g_p1s, g_p1q, 1.f / 32768.f, bn1_g, bn1_b, &sm[A2], &sm[C2], t);

    for (int idx = t; idx < 2592; idx += 512) {
        int co = idx / 216, rem = idx % 216;
        int ci = rem / 9, kh = (rem % 9) / 3, kw = rem % 3;
        sm[W2 + ((ci * 3 + kh) * 4 + co / 3) * 12 + (co % 3) * 3 + kw] =
            w2[((cg * 12 + co) * 24 + ci) * 9 + kh * 3 + kw];
    }
    __syncthreads();   // BN consts ready

    // conflict-free px mapping: 4 rows x 8 cols per warp
    const int w4 = warp & 3;
    const int grp = t >> 7;
    const int wo = (lane & 7) | ((w4 & 1) << 3);
    const int r  = (lane >> 3) | ((w4 >> 1) << 2);

    // stage chunk 0
    if (t < 408) {
        StageV sv;
        stage_quad_load(n, half, 0, t, &sm[A2], &sm[C2], sv);
        stage_quad_store(sm, sv);
    }
    __syncthreads();

    float acc0 = 0.f, acc1 = 0.f, acc2 = 0.f;

#pragma unroll 1
    for (int ck = 0; ck < 4; ck++) {
        StageV sv;
        const bool pf = (ck < 3) && (t < 408);
        if (pf) stage_quad_load(n, half, ck + 1, t, &sm[A2], &sm[C2], sv);

#pragma unroll 2
        for (int cil = 0; cil < 6; cil++) {
            const int ci = ck * 6 + cil;
#pragma unroll
            for (int kh = 0; kh < 3; kh++) {
                const int rl = 2 * r + kh;
                float4 q = *reinterpret_cast<const float4*>(
                    &sm[TQ + cil * 1088 + rl * 64 + wo * 4]);
                const float* wb = &sm[W2 + ((ci * 3 + kh) * 4 + grp) * 12];
                float4 wa = *reinterpret_cast<const float4*>(wb);
                float4 wc = *reinterpret_cast<const float4*>(wb + 4);
                float w8 = wb[8];
                acc0 += q.x * wa.x + q.y * wa.y + q.z * wa.z;
                acc1 += q.x * wa.w + q.y * wc.x + q.z * wc.y;
                acc2 += q.x * wc.z + q.y * wc.w + q.z * w8;
            }
        }
        __syncthreads();
        if (pf) stage_quad_store(sm, sv);
        __syncthreads();
    }

    const int ho = half * 8 + r;
    const int cb = cg * 12 + grp * 3;
    g_y2[((n * 24 + cb + 0) * 16 + ho) * 16 + wo] = acc0;
    g_y2[((n * 24 + cb + 1) * 16 + ho) * 16 + wo] = acc1;
    g_y2[((n * 24 + cb + 2) * 16 + ho) * 16 + wo] = acc2;

    float av[3] = {acc0, acc1, acc2};
#pragma unroll
    for (int c3 = 0; c3 < 3; c3++) {
        float rs = warp_sum(av[c3]);
        float rq = warp_sum(av[c3] * av[c3]);
        if (lane == 0) {
            int ch = grp * 3 + c3;
            sm[RD2 + ch * 8 + w4 * 2] = rs;
            sm[RD2 + ch * 8 + w4 * 2 + 1] = rq;
        }
    }
    __syncthreads();
    if (t < 12) {
        float s = 0.f, q = 0.f;
#pragma unroll
        for (int w = 0; w < 4; w++) { s += sm[RD2 + t * 8 + w * 2]; q += sm[RD2 + t * 8 + w * 2 + 1]; }
        g_p2s[(cg * 12 + t) * 64 + n * 2 + half] = s;
        g_p2q[(cg * 12 + t) * 64 + n * 2 + half] = q;
    }
}

// ============================== head kernel ==============================
#define HQ   0
#define HA   128
#define HC   152
#define HP   176         // 24*16
#define HS   560
#define HRA  592
#define HRB  720
#define HR   1232
#define HH   1360
#define HO   1872

__global__ void __launch_bounds__(512, 1) head_kernel(
    const float* __restrict__ ques,
    const float* __restrict__ bn2_g, const float* __restrict__ bn2_b,
    const float* __restrict__ w_rel, const float* __restrict__ b_rel,
    const float* __restrict__ w_fc1, const float* __restrict__ b_fc1,
    const float* __restrict__ w_fc2, const float* __restrict__ b_fc2,
    float* __restrict__ out) {
    __shared__ __align__(16) float sm[1888];
    const int bid = blockIdx.x, t = threadIdx.x;
    const int warp = t >> 5, lane = t & 31;
    const int n = bid >> 2, chunk = bid & 3;

    compute_bn24(g_p2s, g_p2q, 1.f / 8192.f, bn2_g, bn2_b, &sm[HA], &sm[HC], t);
    if (t >= 384) sm[HQ + t - 384] = ques[n * 128 + t - 384];
    __syncthreads();

    if (t < 384) {
        int c = t >> 4, g = t & 15;
        const float* yp = &g_y2[(n * 24 + c) * 256 + g * 16];
        float a = sm[HA + c], cc = sm[HC + c];
        float acc = 0.f;
#pragma unroll
        for (int i = 0; i < 16; i++) acc += fmaxf(fmaf(a, yp[i], cc), 0.f);
        sm[HP + c * 16 + g] = acc;
    }
    __syncthreads();
    if (t < 26) {
        float s = 0.f;
        if (t < 24) {
#pragma unroll
            for (int g = 0; g < 16; g++) s += sm[HP + t * 16 + g];
        }
        sm[HS + t] = s;
    }
    __syncthreads();

    {
        const int j = t & 127, kk = t >> 7;
        float r2 = (kk == 0) ? b_rel[j] : 0.f;
        const float* wq = &w_rel[(52 + kk * 32) * 128 + j];
#pragma unroll 8
        for (int q = 0; q < 32; q++)
            r2 = fmaf(sm[HQ + kk * 32 + q], wq[q * 128], r2);
        sm[HRB + kk * 128 + j] = r2;
        if (kk == 0) {
            float r1 = 0.f;
#pragma unroll
            for (int k = 0; k < 26; k++)
                r1 += sm[HS + k] * (w_rel[k * 128 + j] + w_rel[(26 + k) * 128 + j]);
            sm[HRA + j] = r1;
        }
    }
    __syncthreads();
    if (t < 128)
        sm[HR + t] = 256.f * sm[HRA + t] +
                     65536.f * (sm[HRB + t] + sm[HRB + 128 + t] +
                                sm[HRB + 256 + t] + sm[HRB + 384 + t]);
    __syncthreads();

    {
        const int jj = t & 255, kh2 = t >> 8;
        const int j = chunk * 256 + jj;
        float acc = (kh2 == 0) ? b_fc1[j] : 0.f;
        const float* wp = &w_fc1[(kh2 * 64) * 1024 + j];
        const float* rp = &sm[HR + kh2 * 64];
#pragma unroll 16
        for (int k = 0; k < 64; k++)
            acc = fmaf(rp[k], wp[k * 1024], acc);
        sm[HH + t] = acc;
    }
    __syncthreads();
    {
        float p0 = 0.f, p1 = 0.f;
        if (t < 256) {
            float hv = fmaxf(sm[HH + t] + sm[HH + t + 256], 0.f);
            const int j = chunk * 256 + t;
            p0 = hv * w_fc2[j * 2];
            p1 = hv * w_fc2[j * 2 + 1];
        }
        p0 = warp_sum(p0);
        p1 = warp_sum(p1);
        if (lane == 0 && warp < 8) { sm[HO + warp * 2] = p0; sm[HO + warp * 2 + 1] = p1; }
    }
    __syncthreads();
    if (t == 0) {
        float o0 = 0.f, o1 = 0.f;
#pragma unroll
        for (int w = 0; w < 8; w++) { o0 += sm[HO + w * 2]; o1 += sm[HO + w * 2 + 1]; }
        g_hpart[(n * 4 + chunk) * 2 + 0] = o0;
        g_hpart[(n * 4 + chunk) * 2 + 1] = o1;
        __threadfence();
        unsigned r = atomicAdd(&g_done[n], 1u);
        if (r == 3) {
            __threadfence();
            float f0 = b_fc2[0], f1 = b_fc2[1];
#pragma unroll
            for (int c = 0; c < 4; c++) {
                f0 += g_hpart[(n * 4 + c) * 2 + 0];
                f1 += g_hpart[(n * 4 + c) * 2 + 1];
            }
            out[n * 2 + 0] = f0;
            out[n * 2 + 1] = f1;
            g_done[n] = 0;
        }
    }
}

// ---------------- launch ----------------
extern "C" void kernel_launch(void* const* d_in, const int* in_sizes, int n_in,
                              void* d_out, int out_size) {
    (void)in_sizes; (void)n_in; (void)out_size;
    const float* image   = (const float*)d_in[0];
    const float* ques    = (const float*)d_in[1];
    const float* conv1_w = (const float*)d_in[2];
    const float* bn1_g   = (const float*)d_in[4];
    const float* bn1_b   = (const float*)d_in[5];
    const float* conv2_w = (const float*)d_in[6];
    const float* bn2_g   = (const float*)d_in[8];
    const float* bn2_b   = (const float*)d_in[9];
    const float* w_rel   = (const float*)d_in[10];
    const float* b_rel   = (const float*)d_in[11];
    const float* w_fc1   = (const float*)d_in[12];
    const float* b_fc1   = (const float*)d_in[13];
    const float* w_fc2   = (const float*)d_in[14];
    const float* b_fc2   = (const float*)d_in[15];
    float* out = (float*)d_out;

    conv1_kernel<<<128, 512>>>(image, conv1_w);
    conv2_kernel<<<128, 512>>>(conv2_w, bn1_g, bn1_b);
    head_kernel<<<128, 512>>>(ques, bn2_g, bn2_b, w_rel, b_rel,
                              w_fc1, b_fc1, w_fc2, b_fc2, out);
}